// round 5
// baseline (speedup 1.0000x reference)
#include <cuda_runtime.h>

// ---------------------------------------------------------------------------
// Problem constants
// ---------------------------------------------------------------------------
#define B_    512
#define T1_   128
#define IN1_  64
#define H1_   256
#define IN3_  32
#define H3_   128
#define T3_   64
#define P_    12
#define FCIN_ 3872
#define FEATC 3840   // feat buffer excludes the trailing current_game(32)

typedef unsigned long long u64;

// ---------------------------------------------------------------------------
// Device scratch (no allocations allowed — static __device__ arrays)
// ---------------------------------------------------------------------------
__device__ __align__(16) float g_WT1[(IN1_ + H1_) * H1_ * 4];   // [k][j][tau]
__device__ __align__(16) float g_WT2[(IN1_ + H1_) * H1_ * 4];
__device__ __align__(16) float g_WT3[(IN3_ + H3_) * H3_ * 4];
__device__ __align__(16) float g_b1[H1_ * 4];                   // [j][tau] (bih+bhh)
__device__ __align__(16) float g_b2[H1_ * 4];
__device__ __align__(16) float g_b3[H3_ * 4];
__device__ float g_feat[B_ * FEATC];

// ---------------------------------------------------------------------------
// f32x2 helpers — 3-reg FFMA is half-rate on sm_103a (rt_SMSP=2);
// fma.rn.f32x2 restores full-rate MACs. ptxas won't emit it from C++.
// ---------------------------------------------------------------------------
__device__ __forceinline__ void fma2(u64& acc, u64 a, u64 b) {
    asm("fma.rn.f32x2 %0, %1, %2, %0;" : "+l"(acc) : "l"(a), "l"(b));
}
__device__ __forceinline__ u64 pack2(float x, float y) {
    u64 u; asm("mov.b64 %0, {%1, %2};" : "=l"(u) : "f"(x), "f"(y)); return u;
}
__device__ __forceinline__ float2 unpack2(u64 u) {
    float lo, hi; asm("mov.b64 {%0, %1}, %2;" : "=f"(lo), "=f"(hi) : "l"(u));
    return make_float2(lo, hi);
}
__device__ __forceinline__ float sigf(float x) {
    return __fdividef(1.0f, 1.0f + __expf(-x));
}
__device__ __forceinline__ float tanhfast(float x) {
    // tanh(x) = 2*sigmoid(2x) - 1  (abs err ~1e-6, fine vs 1e-3 tolerance)
    return fmaf(2.0f, sigf(2.0f * x), -1.0f);
}

// ---------------------------------------------------------------------------
// Weight prep: build WT[k][j][tau] = (k<IN ? Wih : Whh)[tau*H+j][...] and
// bias[j][tau] = bih+bhh. Tiny (~3MB writes).
// ---------------------------------------------------------------------------
__global__ void prep_kernel(
    const float* __restrict__ Wih1, const float* __restrict__ Whh1,
    const float* __restrict__ bih1, const float* __restrict__ bhh1,
    const float* __restrict__ Wih2, const float* __restrict__ Whh2,
    const float* __restrict__ bih2, const float* __restrict__ bhh2,
    const float* __restrict__ Wih3, const float* __restrict__ Whh3,
    const float* __restrict__ bih3, const float* __restrict__ bhh3)
{
    int idx = blockIdx.x * blockDim.x + threadIdx.x;
    const int n1 = (IN1_ + H1_) * H1_ * 4;   // 327680
    const int n3 = (IN3_ + H3_) * H3_ * 4;   // 81920

    if (idx < n1) {
        int tau = idx & 3;
        int t2  = idx >> 2;
        int j   = t2 & (H1_ - 1);
        int k   = t2 >> 8;                   // H1_=256
        int g   = tau * H1_ + j;
        g_WT1[idx] = (k < IN1_) ? Wih1[g * IN1_ + k] : Whh1[g * H1_ + (k - IN1_)];
        g_WT2[idx] = (k < IN1_) ? Wih2[g * IN1_ + k] : Whh2[g * H1_ + (k - IN1_)];
    }
    if (idx < n3) {
        int tau = idx & 3;
        int t2  = idx >> 2;
        int j   = t2 & (H3_ - 1);
        int k   = t2 >> 7;                   // H3_=128
        int g   = tau * H3_ + j;
        g_WT3[idx] = (k < IN3_) ? Wih3[g * IN3_ + k] : Whh3[g * H3_ + (k - IN3_)];
    }
    if (idx < H1_ * 4) {
        int tau = idx & 3, j = idx >> 2;
        g_b1[idx] = bih1[tau * H1_ + j] + bhh1[tau * H1_ + j];
        g_b2[idx] = bih2[tau * H1_ + j] + bhh2[tau * H1_ + j];
    }
    if (idx < H3_ * 4) {
        int tau = idx & 3, j = idx >> 2;
        g_b3[idx] = bih3[tau * H3_ + j] + bhh3[tau * H3_ + j];
    }
}

// ---------------------------------------------------------------------------
// Fused LSTM chunk runner.
// Block = 256 threads. Thread grid: TX = H/2 threads over j (2 j's each),
// TY = 256/TX row-groups, RPT = R/TY rows per thread.
// Each thread owns gates for (RPT rows) x (2 j) x (4 gate types) as f32x2
// pairs, plus the matching c-state in registers — the full LSTM cell update
// happens in-register, h is re-shared via smem (stored duplicated {h,h}).
//
// Arithmetic intensity vs L2: the block reads H*4*4 = 4KB (H=256) of unique
// weight bytes per k and performs R*H*4 MACs against them. R=16 -> 0.25 B/MAC
// (32 B/cyc/SM at fma-bound pace), safely under the ~42 B/cyc/SM LTS share.
// ---------------------------------------------------------------------------
template<int IN, int H, int TT, int R>
__device__ void run_lstm(const float* __restrict__ WT, const float* __restrict__ bias,
                         const float* const* __restrict__ xrow,
                         float* const* __restrict__ hrow,
                         u64* xh2)
{
    constexpr int K   = IN + H;
    constexpr int TX  = H / 2;
    constexpr int TY  = 256 / TX;
    constexpr int RPT = R / TY;

    const int tid = threadIdx.x;
    const int tx  = tid % TX;       // warp-contiguous in tx -> a-loads broadcast
    const int ty  = tid / TX;
    const int j0  = 2 * tx;
    const int r0  = ty * RPT;

    const ulonglong2* __restrict__ Wv = reinterpret_cast<const ulonglong2*>(WT);
    const ulonglong2* __restrict__ bv = reinterpret_cast<const ulonglong2*>(bias);

    // zero the h region of xh2; c-state in registers
    for (int i = tid; i < H * R; i += 256) xh2[IN * R + i] = 0ull;

    u64   acc[RPT][2][2];
    float c[RPT][2];
#pragma unroll
    for (int rr = 0; rr < RPT; rr++) { c[rr][0] = 0.0f; c[rr][1] = 0.0f; }
    __syncthreads();

    const ulonglong2 bias0 = bv[j0];
    const ulonglong2 bias1 = bv[j0 + 1];

    for (int t = 0; t < TT; t++) {
        // load x_t (coalesced per row), store duplicated {v,v}
        for (int i = tid; i < IN * R; i += 256) {
            int r = i / IN, k = i % IN;
            float v = __ldg(xrow[r] + t * IN + k);
            xh2[k * R + r] = pack2(v, v);
        }
        __syncthreads();

#pragma unroll
        for (int rr = 0; rr < RPT; rr++) {
            acc[rr][0][0] = bias0.x; acc[rr][0][1] = bias0.y;
            acc[rr][1][0] = bias1.x; acc[rr][1][1] = bias1.y;
        }

        const ulonglong2* w  = Wv + j0;   // steps by H per k
        const u64*        xk = xh2 + r0;  // steps by R per k
#pragma unroll 4
        for (int k = 0; k < K; k++) {
            ulonglong2 w0 = w[0];   // j0:   (i,f),(g,o)
            ulonglong2 w1 = w[1];   // j0+1: (i,f),(g,o)
#pragma unroll
            for (int rr = 0; rr < RPT; rr++) {
                u64 a = xk[rr];     // {v,v} broadcast
                fma2(acc[rr][0][0], a, w0.x);
                fma2(acc[rr][0][1], a, w0.y);
                fma2(acc[rr][1][0], a, w1.x);
                fma2(acc[rr][1][1], a, w1.y);
            }
            w += H; xk += R;
        }
        __syncthreads();   // all xh2 reads for step t done before h rewrite

        // cell update (PyTorch gate order i,f,g,o)
#pragma unroll
        for (int rr = 0; rr < RPT; rr++) {
#pragma unroll
            for (int jj = 0; jj < 2; jj++) {
                float2 pif = unpack2(acc[rr][jj][0]);   // (i, f)
                float2 pgo = unpack2(acc[rr][jj][1]);   // (g, o)
                float cn = sigf(pif.y) * c[rr][jj] + sigf(pif.x) * tanhfast(pgo.x);
                float h  = sigf(pgo.y) * tanhfast(cn);
                c[rr][jj] = cn;
                xh2[(IN + j0 + jj) * R + (r0 + rr)] = pack2(h, h);
                if (t == TT - 1) hrow[r0 + rr][j0 + jj] = h;
            }
        }
        // next-iter x-load writes only the x region; h writes are ordered
        // against next GEMM reads by the sync after the x-load.
    }
    __syncthreads();   // chunk boundary: xh2/s_x reuse
}

// ---------------------------------------------------------------------------
// Main fused kernel: 128 blocks, each 6 equal work units (1u = 10240 k-iters).
//   LSTM1: 64 chunks (R=16, rows 0..1023 = home||away), 4u each
//   LSTM2: 32 chunks (R=16, rows 0..511), 4u each
//   LSTM3: 384 chunks (R=32, rows 0..12287 = home||away players), 1u each
// Blocks 0..63:  1x LSTM1 + 2x LSTM3
// Blocks 64..95: 1x LSTM2 + 2x LSTM3
// Blocks 96..127: 6x LSTM3
// ---------------------------------------------------------------------------
__global__ __launch_bounds__(256) void lstm_main(
    const float* __restrict__ games_home, const float* __restrict__ games_away,
    const float* __restrict__ games_vs,   const float* __restrict__ players_home,
    const float* __restrict__ players_away)
{
    __shared__ u64 xh2[(IN3_ + H3_) * 32];   // 5120 u64 = 40KB (covers both configs)
    __shared__ const float* s_x[32];
    __shared__ float*       s_h[32];

    const int b   = blockIdx.x;
    const int tid = threadIdx.x;

    int ctype[6], crow[6], nc = 0;
    if (b < 64) {
        ctype[0] = 0; crow[0] = b * 16;
        ctype[1] = 2; crow[1] = (2 * b) * 32;
        ctype[2] = 2; crow[2] = (2 * b + 1) * 32;
        nc = 3;
    } else if (b < 96) {
        ctype[0] = 1; crow[0] = (b - 64) * 16;
        ctype[1] = 2; crow[1] = (2 * b) * 32;        // 128..191 across b=64..95
        ctype[2] = 2; crow[2] = (2 * b + 1) * 32;
        nc = 3;
    } else {
        int q = b - 96;
        for (int i = 0; i < 6; i++) { ctype[nc] = 2; crow[nc++] = (192 + 6 * q + i) * 32; }
    }

    for (int ci = 0; ci < nc; ci++) {
        int type = ctype[ci], row0 = crow[ci];
        if (type == 0) {
            if (tid < 16) {
                int gr = row0 + tid;
                s_x[tid] = (gr < 512) ? games_home + gr * (T1_ * IN1_)
                                      : games_away + (gr - 512) * (T1_ * IN1_);
                s_h[tid] = g_feat + (gr & 511) * FEATC + ((gr < 512) ? 0 : 256);
            }
            __syncthreads();
            run_lstm<IN1_, H1_, T1_, 16>(g_WT1, g_b1, s_x, s_h, xh2);
        } else if (type == 1) {
            if (tid < 16) {
                int gr = row0 + tid;
                s_x[tid] = games_vs + gr * (T1_ * IN1_);
                s_h[tid] = g_feat + gr * FEATC + 512;
            }
            __syncthreads();
            run_lstm<IN1_, H1_, T1_, 16>(g_WT2, g_b2, s_x, s_h, xh2);
        } else {
            if (tid < 32) {
                int gr   = row0 + tid;
                bool hm  = (gr < 6144);
                int  g2  = hm ? gr : gr - 6144;
                int  bb  = g2 / 12;
                int  pp  = g2 - 12 * bb;
                s_x[tid] = (hm ? players_home : players_away) + g2 * (T3_ * IN3_);
                s_h[tid] = g_feat + bb * FEATC + (hm ? 768 : 2304) + pp * H3_;
            }
            __syncthreads();
            run_lstm<IN3_, H3_, T3_, 32>(g_WT3, g_b3, s_x, s_h, xh2);
        }
    }
}

// ---------------------------------------------------------------------------
// Final FC: out[b][o] = feat[b] . Wfc[o] + bfc[o]   (current_game read direct)
// ---------------------------------------------------------------------------
__global__ void fc_kernel(const float* __restrict__ cg, const float* __restrict__ Wfc,
                          const float* __restrict__ bfc, float* __restrict__ out)
{
    const int b = blockIdx.x, tid = threadIdx.x;   // 128 threads
    const float* f = g_feat + b * FEATC;
    float a0 = 0.0f, a1 = 0.0f;
    for (int i = tid; i < FEATC; i += 128) {
        float v = f[i];
        a0 = fmaf(v, Wfc[i], a0);
        a1 = fmaf(v, Wfc[FCIN_ + i], a1);
    }
    if (tid < 32) {
        float v = cg[b * 32 + tid];
        a0 = fmaf(v, Wfc[FEATC + tid], a0);
        a1 = fmaf(v, Wfc[FCIN_ + FEATC + tid], a1);
    }
#pragma unroll
    for (int o = 16; o > 0; o >>= 1) {
        a0 += __shfl_down_sync(0xffffffffu, a0, o);
        a1 += __shfl_down_sync(0xffffffffu, a1, o);
    }
    __shared__ float r0[4], r1[4];
    int w = tid >> 5, l = tid & 31;
    if (l == 0) { r0[w] = a0; r1[w] = a1; }
    __syncthreads();
    if (tid == 0) {
        out[b * 2 + 0] = r0[0] + r0[1] + r0[2] + r0[3] + bfc[0];
        out[b * 2 + 1] = r1[0] + r1[1] + r1[2] + r1[3] + bfc[1];
    }
}

// ---------------------------------------------------------------------------
// kernel_launch
// ---------------------------------------------------------------------------
extern "C" void kernel_launch(void* const* d_in, const int* in_sizes, int n_in,
                              void* d_out, int out_size)
{
    (void)in_sizes; (void)n_in; (void)out_size;
    const float* current_game = (const float*)d_in[0];
    const float* games_home   = (const float*)d_in[1];
    const float* games_away   = (const float*)d_in[2];
    const float* games_vs     = (const float*)d_in[3];
    const float* players_home = (const float*)d_in[4];
    const float* players_away = (const float*)d_in[5];
    const float* Wih1 = (const float*)d_in[6];
    const float* Whh1 = (const float*)d_in[7];
    const float* bih1 = (const float*)d_in[8];
    const float* bhh1 = (const float*)d_in[9];
    const float* Wih2 = (const float*)d_in[10];
    const float* Whh2 = (const float*)d_in[11];
    const float* bih2 = (const float*)d_in[12];
    const float* bhh2 = (const float*)d_in[13];
    const float* Wih3 = (const float*)d_in[14];
    const float* Whh3 = (const float*)d_in[15];
    const float* bih3 = (const float*)d_in[16];
    const float* bhh3 = (const float*)d_in[17];
    const float* Wfc  = (const float*)d_in[18];
    const float* bfc  = (const float*)d_in[19];

    prep_kernel<<<1280, 256>>>(Wih1, Whh1, bih1, bhh1,
                               Wih2, Whh2, bih2, bhh2,
                               Wih3, Whh3, bih3, bhh3);
    lstm_main<<<128, 256>>>(games_home, games_away, games_vs,
                            players_home, players_away);
    fc_kernel<<<512, 128>>>(current_game, Wfc, bfc, (float*)d_out);
}

// round 7
// speedup vs baseline: 1.7228x; 1.7228x over previous
#include <cuda_runtime.h>
#include <cuda_fp16.h>
#include <cstdint>

#define B_    512
#define T1_   128
#define IN1_  64
#define H1_   256
#define IN3_  32
#define H3_   128
#define T3_   64
#define FCIN_ 3872
#define FEATC 3840

typedef unsigned long long u64;
typedef unsigned int u32;

// ---------------- device scratch ----------------
__device__ __align__(16) float g_WT1[(IN1_ + H1_) * H1_ * 4];   // [k][j][tau]
__device__ __align__(16) float g_WT2[(IN1_ + H1_) * H1_ * 4];
__device__ __align__(16) float g_b1[H1_ * 4];                   // [j][tau]
__device__ __align__(16) float g_b2[H1_ * 4];
__device__ __align__(16) float g_b3[H3_ * 4];                   // [j][(bi,bf,bg,bo)]
__device__ float g_feat[B_ * FEATC];

// ---------------- scalar helpers ----------------
__device__ __forceinline__ void fma2(u64& acc, u64 a, u64 b) {
    asm("fma.rn.f32x2 %0, %1, %2, %0;" : "+l"(acc) : "l"(a), "l"(b));
}
__device__ __forceinline__ u64 pack2(float x, float y) {
    u64 u; asm("mov.b64 %0, {%1, %2};" : "=l"(u) : "f"(x), "f"(y)); return u;
}
__device__ __forceinline__ float2 unpack2(u64 u) {
    float lo, hi; asm("mov.b64 {%0, %1}, %2;" : "=f"(lo), "=f"(hi) : "l"(u));
    return make_float2(lo, hi);
}
__device__ __forceinline__ float sigf(float x) {
    return __fdividef(1.0f, 1.0f + __expf(-x));
}
__device__ __forceinline__ float tanhfast(float x) {
    return fmaf(2.0f, sigf(2.0f * x), -1.0f);
}
__device__ __forceinline__ float tapx(float x) {           // HW tanh (MUFU)
    float y; asm("tanh.approx.f32 %0, %1;" : "=f"(y) : "f"(x)); return y;
}
__device__ __forceinline__ float sga(float x) {            // sigmoid via tanh
    return fmaf(tapx(0.5f * x), 0.5f, 0.5f);
}
__device__ __forceinline__ u32 smem_u32(const void* p) {
    u32 a;
    asm("{ .reg .u64 t; cvta.to.shared.u64 t, %1; cvt.u32.u64 %0, t; }" : "=r"(a) : "l"(p));
    return a;
}

// ---------------- mma.sync / ldmatrix (baseline PTX, no 'a'-target needed) --
__device__ __forceinline__ void ldsm_x4(u32& r0, u32& r1, u32& r2, u32& r3, u32 addr) {
    asm volatile("ldmatrix.sync.aligned.m8n8.x4.shared.b16 {%0,%1,%2,%3}, [%4];"
                 : "=r"(r0), "=r"(r1), "=r"(r2), "=r"(r3) : "r"(addr));
}
__device__ __forceinline__ void ldsm_x2t(u32& r0, u32& r1, u32 addr) {
    asm volatile("ldmatrix.sync.aligned.m8n8.x2.trans.shared.b16 {%0,%1}, [%2];"
                 : "=r"(r0), "=r"(r1) : "r"(addr));
}
__device__ __forceinline__ void mma16816(float* c, u32 a0, u32 a1, u32 a2, u32 a3,
                                         u32 b0, u32 b1) {
    asm volatile("mma.sync.aligned.m16n8k16.row.col.f32.f16.f16.f32 "
                 "{%0,%1,%2,%3}, {%4,%5,%6,%7}, {%8,%9}, {%0,%1,%2,%3};"
                 : "+f"(c[0]), "+f"(c[1]), "+f"(c[2]), "+f"(c[3])
                 : "r"(a0), "r"(a1), "r"(a2), "r"(a3), "r"(b0), "r"(b1));
}

// lstm3_mma smem layout
#define ASTRIDE 336            // 32 rows x 336B (conflict-free ldmatrix)
#define BSTRIDE 1040           // 160 k-rows x 1040B, n-contiguous fp16 [k][n]
#define SMB_A    0             // 10752
#define SMB_BIAS 10752         // 2048 (float4[128])
#define SMB_B    12800         // 166400
#define SMEM3    179200

// ---------------- weight prep ----------------
__global__ void prep_kernel(
    const float* __restrict__ Wih1, const float* __restrict__ Whh1,
    const float* __restrict__ bih1, const float* __restrict__ bhh1,
    const float* __restrict__ Wih2, const float* __restrict__ Whh2,
    const float* __restrict__ bih2, const float* __restrict__ bhh2,
    const float* __restrict__ bih3, const float* __restrict__ bhh3)
{
    int idx = blockIdx.x * blockDim.x + threadIdx.x;
    const int n1 = (IN1_ + H1_) * H1_ * 4;
    if (idx < n1) {
        int tau = idx & 3;
        int t2  = idx >> 2;
        int j   = t2 & (H1_ - 1);
        int k   = t2 >> 8;
        int g   = tau * H1_ + j;
        g_WT1[idx] = (k < IN1_) ? Wih1[g * IN1_ + k] : Whh1[g * H1_ + (k - IN1_)];
        g_WT2[idx] = (k < IN1_) ? Wih2[g * IN1_ + k] : Whh2[g * H1_ + (k - IN1_)];
    }
    if (idx < H1_ * 4) {
        int tau = idx & 3, j = idx >> 2;
        g_b1[idx] = bih1[tau * H1_ + j] + bhh1[tau * H1_ + j];
        g_b2[idx] = bih2[tau * H1_ + j] + bhh2[tau * H1_ + j];
    }
    if (idx < H3_ * 4) {
        int tau = idx & 3, j = idx >> 2;
        g_b3[j * 4 + tau] = bih3[tau * H3_ + j] + bhh3[tau * H3_ + j];
    }
}

// ---------------- FFMA LSTM runner (LSTM1/2, R=8, proven) ----------------
template<int IN, int H, int TT, int R>
__device__ void run_lstm(const float* __restrict__ WT, const float* __restrict__ bias,
                         const float* const* __restrict__ xrow,
                         float* const* __restrict__ hrow, u64* xh2)
{
    constexpr int K   = IN + H;
    constexpr int TX  = H / 2;
    constexpr int TY  = 256 / TX;
    constexpr int RPT = R / TY;

    const int tid = threadIdx.x;
    const int tx  = tid % TX;
    const int ty  = tid / TX;
    const int j0  = 2 * tx;
    const int r0  = ty * RPT;

    const ulonglong2* __restrict__ Wv = reinterpret_cast<const ulonglong2*>(WT);
    const ulonglong2* __restrict__ bv = reinterpret_cast<const ulonglong2*>(bias);

    for (int i = tid; i < H * R; i += 256) xh2[IN * R + i] = 0ull;

    u64   acc[RPT][2][2];
    float c[RPT][2];
#pragma unroll
    for (int rr = 0; rr < RPT; rr++) { c[rr][0] = 0.0f; c[rr][1] = 0.0f; }
    __syncthreads();

    const ulonglong2 bias0 = bv[j0];
    const ulonglong2 bias1 = bv[j0 + 1];

    for (int t = 0; t < TT; t++) {
        for (int i = tid; i < IN * R; i += 256) {
            int r = i / IN, k = i % IN;
            float v = __ldg(xrow[r] + t * IN + k);
            xh2[k * R + r] = pack2(v, v);
        }
        __syncthreads();

#pragma unroll
        for (int rr = 0; rr < RPT; rr++) {
            acc[rr][0][0] = bias0.x; acc[rr][0][1] = bias0.y;
            acc[rr][1][0] = bias1.x; acc[rr][1][1] = bias1.y;
        }

        const ulonglong2* w  = Wv + j0;
        const u64*        xk = xh2 + r0;
#pragma unroll 4
        for (int k = 0; k < K; k++) {
            ulonglong2 w0 = w[0];
            ulonglong2 w1 = w[1];
#pragma unroll
            for (int rr = 0; rr < RPT; rr++) {
                u64 a = xk[rr];
                fma2(acc[rr][0][0], a, w0.x);
                fma2(acc[rr][0][1], a, w0.y);
                fma2(acc[rr][1][0], a, w1.x);
                fma2(acc[rr][1][1], a, w1.y);
            }
            w += H; xk += R;
        }
        __syncthreads();

#pragma unroll
        for (int rr = 0; rr < RPT; rr++) {
#pragma unroll
            for (int jj = 0; jj < 2; jj++) {
                float2 pif = unpack2(acc[rr][jj][0]);
                float2 pgo = unpack2(acc[rr][jj][1]);
                float cn = sigf(pif.y) * c[rr][jj] + sigf(pif.x) * tanhfast(pgo.x);
                float h  = sigf(pgo.y) * tanhfast(cn);
                c[rr][jj] = cn;
                xh2[(IN + j0 + jj) * R + (r0 + rr)] = pack2(h, h);
                if (t == TT - 1) hrow[r0 + rr][j0 + jj] = h;
            }
        }
    }
    __syncthreads();
}

// ---------------- LSTM1/2 kernel: 192 blocks ----------------
__global__ __launch_bounds__(256) void lstm12_kernel(
    const float* __restrict__ games_home, const float* __restrict__ games_away,
    const float* __restrict__ games_vs)
{
    __shared__ u64 xh2[(IN1_ + H1_) * 8];
    __shared__ const float* s_x[8];
    __shared__ float*       s_h[8];
    const int b = blockIdx.x, tid = threadIdx.x;

    if (b < 128) {
        if (tid < 8) {
            int gr = b * 8 + tid;
            s_x[tid] = (gr < 512) ? games_home + gr * (T1_ * IN1_)
                                  : games_away + (gr - 512) * (T1_ * IN1_);
            s_h[tid] = g_feat + (gr & 511) * FEATC + ((gr < 512) ? 0 : 256);
        }
        __syncthreads();
        run_lstm<IN1_, H1_, T1_, 8>(g_WT1, g_b1, s_x, s_h, xh2);
    } else {
        if (tid < 8) {
            int gr = (b - 128) * 8 + tid;
            s_x[tid] = games_vs + gr * (T1_ * IN1_);
            s_h[tid] = g_feat + gr * FEATC + 512;
        }
        __syncthreads();
        run_lstm<IN1_, H1_, T1_, 8>(g_WT2, g_b2, s_x, s_h, xh2);
    }
}

// ---------------------------------------------------------------------------
// LSTM3 via mma.sync: 384 blocks x 32 rows, 8 warps.
// A[32][160] fp16 (336B pitch): k<32 = x_t, k>=32 = h_{t-1}.
// B[k=160][n=512] fp16 (1040B pitch, n = gate*128 + j), smem-resident all steps.
// Warp w: rows [rt*16, rt*16+16) (rt=w>>2), j in [jq*32, jq*32+32) (jq=w&3).
// Lane: g=lane>>2, tig=lane&3; fragment rows {rt*16+g, +8}, cols j = jq*32+sub*8+2*tig+{0,1}.
// Accum acc[gate][sub][c]: same (row,col) offsets in all 4 gate tiles -> cell
// update fully lane-local; c,h live in registers; h re-written to A as half2.
// ---------------------------------------------------------------------------
__global__ __launch_bounds__(256, 1) void lstm3_mma(
    const float* __restrict__ ph, const float* __restrict__ pa,
    const float* __restrict__ Wih3, const float* __restrict__ Whh3)
{
    extern __shared__ __align__(16) char sm[];
    const u32 sbase = smem_u32(sm);
    const int tid = threadIdx.x, wid = tid >> 5, lane = tid & 31;
    const int row0 = blockIdx.x * 32;

    // ---- B fill: B[k][n] = (k<32 ? Wih3[n][k] : Whh3[n][k-32]) ----
    for (int idx = tid; idx < 512 * 160; idx += 256) {
        int n = idx / 160, k = idx - n * 160;
        float v = (k < IN3_) ? Wih3[n * IN3_ + k] : Whh3[n * H3_ + (k - IN3_)];
        *(__half*)(sm + SMB_B + k * BSTRIDE + n * 2) = __float2half_rn(v);
    }
    // ---- bias float4[j] ----
    for (int i = tid; i < 512; i += 256)
        ((float*)(sm + SMB_BIAS))[i] = g_b3[i];

    // ---- x loader mapping: 8 threads/row, 4 floats each ----
    const int xr = tid >> 3, xq = tid & 7;
    const int gxr = row0 + xr;
    const bool hmx = (gxr < 6144);
    const int gx2 = hmx ? gxr : gxr - 6144;
    const float4* xsrc = (const float4*)((hmx ? ph : pa) + (size_t)gx2 * (T3_ * IN3_)) + xq;
    char* xdst = sm + SMB_A + xr * ASTRIDE + xq * 8;

    // ---- warp tiling ----
    const int rt = wid >> 2, jq = wid & 3;
    const int g = lane >> 2, tig = lane & 3;

    // ldmatrix addresses
    const u32 a_addr = sbase + SMB_A + (u32)((rt * 16 + (lane & 15)) * ASTRIDE + (lane >> 4) * 16);
    const u32 b_addr = sbase + SMB_B + (u32)((lane & 15) * BSTRIDE);

    // h smem store addresses (two rows x 4 sub, half2 each)
    char* hs_lo = sm + SMB_A + (rt * 16 + g) * ASTRIDE + (IN3_ + jq * 32 + 2 * tig) * 2;
    char* hs_hi = hs_lo + 8 * ASTRIDE;

    float acc[4][4][4];
    float cst[16], hreg[16];
#pragma unroll
    for (int i = 0; i < 16; i++) { cst[i] = 0.0f; hreg[i] = 0.0f; }

    __syncthreads();   // B, bias ready

    for (int t = 0; t < T3_; t++) {
        // ---- phase 1: store x_t and h_{t-1} into A ----
        float4 xv = __ldg(xsrc + t * 8);
        *(__half2*)(xdst)     = __floats2half2_rn(xv.x, xv.y);
        *(__half2*)(xdst + 4) = __floats2half2_rn(xv.z, xv.w);
#pragma unroll
        for (int sub = 0; sub < 4; sub++) {
            *(__half2*)(hs_lo + sub * 16) = __floats2half2_rn(hreg[sub * 4 + 0], hreg[sub * 4 + 1]);
            *(__half2*)(hs_hi + sub * 16) = __floats2half2_rn(hreg[sub * 4 + 2], hreg[sub * 4 + 3]);
        }
        __syncthreads();

        // ---- phase 2: MMA D[32,512] = A[32,160] x B ----
#pragma unroll
        for (int i = 0; i < 64; i++) ((float*)acc)[i] = 0.0f;

#pragma unroll
        for (int kt = 0; kt < 10; kt++) {
            u32 a0, a1, a2, a3;
            ldsm_x4(a0, a1, a2, a3, a_addr + kt * 32);
#pragma unroll
            for (int gi = 0; gi < 4; gi++) {
#pragma unroll
                for (int sub = 0; sub < 4; sub++) {
                    u32 b0, b1;
                    ldsm_x2t(b0, b1, b_addr + (u32)(kt * 16 * BSTRIDE + (gi * 128 + jq * 32 + sub * 8) * 2));
                    mma16816(acc[gi][sub], a0, a1, a2, a3, b0, b1);
                }
            }
        }
        __syncthreads();   // all A reads done before next-step h/x stores

        // ---- phase 3: cell update (registers only) ----
        const float4* bias4 = (const float4*)(sm + SMB_BIAS);
#pragma unroll
        for (int sub = 0; sub < 4; sub++) {
            const int jb = jq * 32 + sub * 8 + 2 * tig;
#pragma unroll
            for (int cc = 0; cc < 4; cc++) {
                int j = jb + (cc & 1);
                float4 b4 = bias4[j];
                float iv = sga(acc[0][sub][cc] + b4.x);
                float fv = sga(acc[1][sub][cc] + b4.y);
                float gv = tapx(acc[2][sub][cc] + b4.z);
                float ov = sga(acc[3][sub][cc] + b4.w);
                int ci = sub * 4 + cc;
                float cn = fv * cst[ci] + iv * gv;
                cst[ci] = cn;
                hreg[ci] = ov * tapx(cn);
            }
        }
    }

    // ---- final h -> g_feat ----
#pragma unroll
    for (int half = 0; half < 2; half++) {
        int gr = row0 + rt * 16 + g + half * 8;
        bool hm = (gr < 6144);
        int g2 = hm ? gr : gr - 6144;
        int bb = g2 / 12, pp = g2 - 12 * bb;
        float* fp = g_feat + (size_t)bb * FEATC + (hm ? 768 : 2304) + pp * H3_;
#pragma unroll
        for (int sub = 0; sub < 4; sub++) {
            int j = jq * 32 + sub * 8 + 2 * tig;
            fp[j]     = hreg[sub * 4 + half * 2 + 0];
            fp[j + 1] = hreg[sub * 4 + half * 2 + 1];
        }
    }
}

// ---------------- FC ----------------
__global__ void fc_kernel(const float* __restrict__ cg, const float* __restrict__ Wfc,
                          const float* __restrict__ bfc, float* __restrict__ out)
{
    const int b = blockIdx.x, tid = threadIdx.x;   // 128 threads
    const float* f = g_feat + b * FEATC;
    float a0 = 0.0f, a1 = 0.0f;
    for (int i = tid; i < FEATC; i += 128) {
        float v = f[i];
        a0 = fmaf(v, Wfc[i], a0);
        a1 = fmaf(v, Wfc[FCIN_ + i], a1);
    }
    if (tid < 32) {
        float v = cg[b * 32 + tid];
        a0 = fmaf(v, Wfc[FEATC + tid], a0);
        a1 = fmaf(v, Wfc[FCIN_ + FEATC + tid], a1);
    }
#pragma unroll
    for (int o = 16; o > 0; o >>= 1) {
        a0 += __shfl_down_sync(0xffffffffu, a0, o);
        a1 += __shfl_down_sync(0xffffffffu, a1, o);
    }
    __shared__ float r0[4], r1[4];
    int w = tid >> 5, l = tid & 31;
    if (l == 0) { r0[w] = a0; r1[w] = a1; }
    __syncthreads();
    if (tid == 0) {
        out[b * 2 + 0] = r0[0] + r0[1] + r0[2] + r0[3] + bfc[0];
        out[b * 2 + 1] = r1[0] + r1[1] + r1[2] + r1[3] + bfc[1];
    }
}

// ---------------- kernel_launch ----------------
extern "C" void kernel_launch(void* const* d_in, const int* in_sizes, int n_in,
                              void* d_out, int out_size)
{
    (void)in_sizes; (void)n_in; (void)out_size;
    const float* current_game = (const float*)d_in[0];
    const float* games_home   = (const float*)d_in[1];
    const float* games_away   = (const float*)d_in[2];
    const float* games_vs     = (const float*)d_in[3];
    const float* players_home = (const float*)d_in[4];
    const float* players_away = (const float*)d_in[5];
    const float* Wih1 = (const float*)d_in[6];
    const float* Whh1 = (const float*)d_in[7];
    const float* bih1 = (const float*)d_in[8];
    const float* bhh1 = (const float*)d_in[9];
    const float* Wih2 = (const float*)d_in[10];
    const float* Whh2 = (const float*)d_in[11];
    const float* bih2 = (const float*)d_in[12];
    const float* bhh2 = (const float*)d_in[13];
    const float* Wih3 = (const float*)d_in[14];
    const float* Whh3 = (const float*)d_in[15];
    const float* bih3 = (const float*)d_in[16];
    const float* bhh3 = (const float*)d_in[17];
    const float* Wfc  = (const float*)d_in[18];
    const float* bfc  = (const float*)d_in[19];

    cudaFuncSetAttribute(lstm3_mma, cudaFuncAttributeMaxDynamicSharedMemorySize, SMEM3);

    prep_kernel<<<1280, 256>>>(Wih1, Whh1, bih1, bhh1,
                               Wih2, Whh2, bih2, bhh2, bih3, bhh3);
    lstm3_mma<<<384, 256, SMEM3>>>(players_home, players_away, Wih3, Whh3);
    lstm12_kernel<<<192, 256>>>(games_home, games_away, games_vs);
    fc_kernel<<<512, 128>>>(current_game, Wfc, bfc, (float*)d_out);
}

// round 8
// speedup vs baseline: 5.9951x; 3.4799x over previous
#include <cuda_runtime.h>
#include <cuda_fp16.h>
#include <cstdint>

#define B_    512
#define T1_   128
#define IN1_  64
#define H1_   256
#define IN3_  32
#define H3_   128
#define T3_   64
#define FCIN_ 3872
#define FEATC 3840

typedef unsigned long long u64;
typedef unsigned int u32;

// ---------------- device scratch ----------------
__device__ __align__(16) __half g_W1h[320 * 1024];   // [k][n], n=gate*256+j, pitch 2048B
__device__ __align__(16) __half g_W2h[320 * 1024];
__device__ __align__(16) float4 g_b1v4[H1_];         // (bi,bf,bg,bo) per j
__device__ __align__(16) float4 g_b2v4[H1_];
__device__ __align__(16) float  g_b3[H3_ * 4];       // [j][(bi,bf,bg,bo)]
__device__ float g_feat[B_ * FEATC];

// ---------------- scalar helpers ----------------
__device__ __forceinline__ float tapx(float x) {           // HW tanh (MUFU)
    float y; asm("tanh.approx.f32 %0, %1;" : "=f"(y) : "f"(x)); return y;
}
__device__ __forceinline__ float sga(float x) {            // sigmoid via tanh
    return fmaf(tapx(0.5f * x), 0.5f, 0.5f);
}
__device__ __forceinline__ u32 smem_u32(const void* p) {
    u32 a;
    asm("{ .reg .u64 t; cvta.to.shared.u64 t, %1; cvt.u32.u64 %0, t; }" : "=r"(a) : "l"(p));
    return a;
}

// ---------------- mma.sync / ldmatrix / cp.async (baseline PTX) ----------------
__device__ __forceinline__ void ldsm_x4(u32& r0, u32& r1, u32& r2, u32& r3, u32 addr) {
    asm volatile("ldmatrix.sync.aligned.m8n8.x4.shared.b16 {%0,%1,%2,%3}, [%4];"
                 : "=r"(r0), "=r"(r1), "=r"(r2), "=r"(r3) : "r"(addr));
}
__device__ __forceinline__ void ldsm_x2t(u32& r0, u32& r1, u32 addr) {
    asm volatile("ldmatrix.sync.aligned.m8n8.x2.trans.shared.b16 {%0,%1}, [%2];"
                 : "=r"(r0), "=r"(r1) : "r"(addr));
}
__device__ __forceinline__ void mma16816(float* c, u32 a0, u32 a1, u32 a2, u32 a3,
                                         u32 b0, u32 b1) {
    asm volatile("mma.sync.aligned.m16n8k16.row.col.f32.f16.f16.f32 "
                 "{%0,%1,%2,%3}, {%4,%5,%6,%7}, {%8,%9}, {%0,%1,%2,%3};"
                 : "+f"(c[0]), "+f"(c[1]), "+f"(c[2]), "+f"(c[3])
                 : "r"(a0), "r"(a1), "r"(a2), "r"(a3), "r"(b0), "r"(b1));
}
__device__ __forceinline__ void cp16(u32 saddr, const void* gptr) {
    asm volatile("cp.async.cg.shared.global [%0], [%1], 16;" :: "r"(saddr), "l"(gptr));
}
__device__ __forceinline__ void cp_commit() {
    asm volatile("cp.async.commit_group;" ::: "memory");
}
template<int N> __device__ __forceinline__ void cp_wait() {
    asm volatile("cp.async.wait_group %0;" :: "n"(N) : "memory");
}

// ---------------- lstm3 smem layout (unchanged, proven) ----------------
#define ASTRIDE 336
#define BSTRIDE 1040
#define SMB_A    0
#define SMB_BIAS 10752
#define SMB_B    12800
#define SMEM3    179200

// ---------------- lstm12 smem layout ----------------
#define APITCH12  656              // 16 rows x 656B (320 halves + pad)
#define BPITCH12  2064             // 32 k-rows x 2064B per tile
#define TILE12    66048            // 32*2064
#define SM12_A    0                // 10496
#define SM12_BIAS 10496            // 4096 (float4[256])
#define SM12_B0   14592
#define SM12_B1   (14592 + TILE12)
#define SMEM12    (14592 + 2 * TILE12)   // 146688

// ---------------- weight prep ----------------
__global__ void prep_kernel(
    const float* __restrict__ Wih1, const float* __restrict__ Whh1,
    const float* __restrict__ bih1, const float* __restrict__ bhh1,
    const float* __restrict__ Wih2, const float* __restrict__ Whh2,
    const float* __restrict__ bih2, const float* __restrict__ bhh2,
    const float* __restrict__ bih3, const float* __restrict__ bhh3)
{
    int idx = blockIdx.x * blockDim.x + threadIdx.x;   // 327680 threads
    if (idx < 320 * 1024) {
        int k = idx >> 10, n = idx & 1023;
        int tau = n >> 8, j = n & 255;
        int g = tau * H1_ + j;
        float v1 = (k < IN1_) ? Wih1[g * IN1_ + k] : Whh1[g * H1_ + (k - IN1_)];
        float v2 = (k < IN1_) ? Wih2[g * IN1_ + k] : Whh2[g * H1_ + (k - IN1_)];
        g_W1h[idx] = __float2half_rn(v1);
        g_W2h[idx] = __float2half_rn(v2);
    }
    if (idx < H1_) {
        int j = idx;
        g_b1v4[j] = make_float4(bih1[j] + bhh1[j],
                                bih1[H1_ + j] + bhh1[H1_ + j],
                                bih1[2 * H1_ + j] + bhh1[2 * H1_ + j],
                                bih1[3 * H1_ + j] + bhh1[3 * H1_ + j]);
        g_b2v4[j] = make_float4(bih2[j] + bhh2[j],
                                bih2[H1_ + j] + bhh2[H1_ + j],
                                bih2[2 * H1_ + j] + bhh2[2 * H1_ + j],
                                bih2[3 * H1_ + j] + bhh2[3 * H1_ + j]);
    }
    if (idx < H3_ * 4) {
        int tau = idx & 3, j = idx >> 2;
        g_b3[j * 4 + tau] = bih3[tau * H3_ + j] + bhh3[tau * H3_ + j];
    }
}

// ---------------------------------------------------------------------------
// LSTM1/2 via mma.sync + cp.async-streamed B.
// 96 blocks x 16 rows, 8 warps (256 thr). K=320, N=1024 (4 gates x 256 j).
// A[16][320] fp16 (656B pitch): k<64 = x_t, k>=64 = h_{t-1}.
// B streamed as 10 circular tiles (32k x 1024n fp16, 2064B pitch), 2 buffers,
// prefetch distance 2. B is t-invariant so the stream wraps across steps.
// Warp jq (0..7): j in [jq*32, jq*32+32) for ALL 4 gates -> lane-local cell
// update. Lane: g=lane>>2, tig=lane&3; rows {g, g+8}; j = jq*32+sub*8+2tig+{0,1}.
// ---------------------------------------------------------------------------
__global__ __launch_bounds__(256, 1) void lstm12_mma(
    const float* __restrict__ games_home, const float* __restrict__ games_away,
    const float* __restrict__ games_vs)
{
    extern __shared__ __align__(16) char sm[];
    const u32 sbase = smem_u32(sm);
    const int tid = threadIdx.x, wid = tid >> 5, lane = tid & 31;
    const int b = blockIdx.x;
    const bool is1 = (b < 64);
    const int row0 = (is1 ? b : (b - 64)) * 16;

    const char* gB = (const char*)(is1 ? g_W1h : g_W2h);
    const float4* gbias = is1 ? g_b1v4 : g_b2v4;

    // ---- bias -> smem ----
    if (tid < H1_) ((float4*)(sm + SM12_BIAS))[tid] = gbias[tid];
    // ---- zero A (h0 = 0) ----
    for (int i = tid; i < 16 * APITCH12 / 8; i += 256) ((u64*)(sm + SM12_A))[i] = 0ull;

    // ---- x loader mapping: 16 threads/row, float4 each ----
    const int xr = tid >> 4, xq = tid & 15;
    const int gxr = row0 + xr;
    const float* xrowp = is1 ? ((gxr < 512) ? games_home + (size_t)gxr * (T1_ * IN1_)
                                            : games_away + (size_t)(gxr - 512) * (T1_ * IN1_))
                             : games_vs + (size_t)gxr * (T1_ * IN1_);
    const float4* xsrc = (const float4*)xrowp + xq;
    char* xdst = sm + SM12_A + xr * APITCH12 + xq * 8;

    // ---- warp tiling ----
    const int jq = wid;
    const int g = lane >> 2, tig = lane & 3;
    const u32 a_addr = sbase + SM12_A + (u32)((lane & 15) * APITCH12 + (lane >> 4) * 16);
    const u32 b_lane = (u32)((lane & 15) * BPITCH12);

    // h store addrs in A (k = 64 + j)
    char* hs_lo = sm + SM12_A + g * APITCH12 + (IN1_ + jq * 32 + 2 * tig) * 2;
    char* hs_hi = hs_lo + 8 * APITCH12;

    float acc[4][4][4];
    float cst[16], hreg[16];
#pragma unroll
    for (int i = 0; i < 16; i++) { cst[i] = 0.0f; hreg[i] = 0.0f; }

    // ---- prefetch tiles 0,1 ----
    const u32 bufs[2] = { sbase + SM12_B0, sbase + SM12_B1 };
#pragma unroll
    for (int pt = 0; pt < 2; pt++) {
#pragma unroll
        for (int q = 0; q < 16; q++) {
            int c = tid + 256 * q;          // 4096 chunks of 16B
            int row = c >> 7, col = (c & 127) * 16;
            cp16(bufs[pt] + (u32)(row * BPITCH12 + col), gB + (pt * 32 + row) * 2048 + col);
        }
        cp_commit();
    }
    __syncthreads();

    for (int t = 0; t < T1_; t++) {
        // ---- phase 1: x_t + h_{t-1} -> A ----
        float4 xv = __ldg(xsrc + t * 16);
        *(__half2*)(xdst)     = __floats2half2_rn(xv.x, xv.y);
        *(__half2*)(xdst + 4) = __floats2half2_rn(xv.z, xv.w);
#pragma unroll
        for (int sub = 0; sub < 4; sub++) {
            *(__half2*)(hs_lo + sub * 16) = __floats2half2_rn(hreg[sub * 4 + 0], hreg[sub * 4 + 1]);
            *(__half2*)(hs_hi + sub * 16) = __floats2half2_rn(hreg[sub * 4 + 2], hreg[sub * 4 + 3]);
        }
        __syncthreads();

#pragma unroll
        for (int i = 0; i < 64; i++) ((float*)acc)[i] = 0.0f;

        // ---- phase 2: K loop over 10 streamed tiles of 32 k ----
        for (int kt = 0; kt < 10; kt++) {
            const u32 buf = bufs[kt & 1];
            cp_wait<1>();                    // tile kt landed
            __syncthreads();
#pragma unroll
            for (int ks = 0; ks < 2; ks++) {
                u32 a0, a1, a2, a3;
                ldsm_x4(a0, a1, a2, a3, a_addr + (u32)((kt * 2 + ks) * 32));
                const u32 bk = buf + b_lane + (u32)(ks * 16 * BPITCH12);
#pragma unroll
                for (int gi = 0; gi < 4; gi++) {
#pragma unroll
                    for (int sub = 0; sub < 4; sub++) {
                        u32 b0, b1;
                        ldsm_x2t(b0, b1, bk + (u32)((gi * 256 + jq * 32 + sub * 8) * 2));
                        mma16816(acc[gi][sub], a0, a1, a2, a3, b0, b1);
                    }
                }
            }
            __syncthreads();                 // reads of buf done -> safe to refill
            int nt = (kt + 2) % 10;          // circular: wraps into next step
#pragma unroll
            for (int q = 0; q < 16; q++) {
                int c = tid + 256 * q;
                int row = c >> 7, col = (c & 127) * 16;
                cp16(buf + (u32)(row * BPITCH12 + col), gB + (nt * 32 + row) * 2048 + col);
            }
            cp_commit();
        }

        // ---- phase 3: cell update (registers only) ----
        const float4* bias4 = (const float4*)(sm + SM12_BIAS);
#pragma unroll
        for (int sub = 0; sub < 4; sub++) {
            const int jb = jq * 32 + sub * 8 + 2 * tig;
#pragma unroll
            for (int cc = 0; cc < 4; cc++) {
                int j = jb + (cc & 1);
                float4 b4 = bias4[j];
                float iv = sga(acc[0][sub][cc] + b4.x);
                float fv = sga(acc[1][sub][cc] + b4.y);
                float gv = tapx(acc[2][sub][cc] + b4.z);
                float ov = sga(acc[3][sub][cc] + b4.w);
                int ci = sub * 4 + cc;
                float cn = fv * cst[ci] + iv * gv;
                cst[ci] = cn;
                hreg[ci] = ov * tapx(cn);
            }
        }
    }

    // ---- final h -> g_feat ----
#pragma unroll
    for (int half = 0; half < 2; half++) {
        int gr = row0 + g + half * 8;
        float* fp;
        if (is1) fp = g_feat + (size_t)(gr & 511) * FEATC + ((gr < 512) ? 0 : 256);
        else     fp = g_feat + (size_t)gr * FEATC + 512;
#pragma unroll
        for (int sub = 0; sub < 4; sub++) {
            int j = jq * 32 + sub * 8 + 2 * tig;
            fp[j]     = hreg[sub * 4 + half * 2 + 0];
            fp[j + 1] = hreg[sub * 4 + half * 2 + 1];
        }
    }
}

// ---------------------------------------------------------------------------
// LSTM3 via mma.sync (unchanged from R7, proven): 384 blocks x 32 rows, 8 warps
// ---------------------------------------------------------------------------
__global__ __launch_bounds__(256, 1) void lstm3_mma(
    const float* __restrict__ ph, const float* __restrict__ pa,
    const float* __restrict__ Wih3, const float* __restrict__ Whh3)
{
    extern __shared__ __align__(16) char sm[];
    const u32 sbase = smem_u32(sm);
    const int tid = threadIdx.x, wid = tid >> 5, lane = tid & 31;
    const int row0 = blockIdx.x * 32;

    for (int idx = tid; idx < 512 * 160; idx += 256) {
        int n = idx / 160, k = idx - n * 160;
        float v = (k < IN3_) ? Wih3[n * IN3_ + k] : Whh3[n * H3_ + (k - IN3_)];
        *(__half*)(sm + SMB_B + k * BSTRIDE + n * 2) = __float2half_rn(v);
    }
    for (int i = tid; i < 512; i += 256)
        ((float*)(sm + SMB_BIAS))[i] = g_b3[i];

    const int xr = tid >> 3, xq = tid & 7;
    const int gxr = row0 + xr;
    const bool hmx = (gxr < 6144);
    const int gx2 = hmx ? gxr : gxr - 6144;
    const float4* xsrc = (const float4*)((hmx ? ph : pa) + (size_t)gx2 * (T3_ * IN3_)) + xq;
    char* xdst = sm + SMB_A + xr * ASTRIDE + xq * 8;

    const int rt = wid >> 2, jq = wid & 3;
    const int g = lane >> 2, tig = lane & 3;

    const u32 a_addr = sbase + SMB_A + (u32)((rt * 16 + (lane & 15)) * ASTRIDE + (lane >> 4) * 16);
    const u32 b_addr = sbase + SMB_B + (u32)((lane & 15) * BSTRIDE);

    char* hs_lo = sm + SMB_A + (rt * 16 + g) * ASTRIDE + (IN3_ + jq * 32 + 2 * tig) * 2;
    char* hs_hi = hs_lo + 8 * ASTRIDE;

    float acc[4][4][4];
    float cst[16], hreg[16];
#pragma unroll
    for (int i = 0; i < 16; i++) { cst[i] = 0.0f; hreg[i] = 0.0f; }

    __syncthreads();

    for (int t = 0; t < T3_; t++) {
        float4 xv = __ldg(xsrc + t * 8);
        *(__half2*)(xdst)     = __floats2half2_rn(xv.x, xv.y);
        *(__half2*)(xdst + 4) = __floats2half2_rn(xv.z, xv.w);
#pragma unroll
        for (int sub = 0; sub < 4; sub++) {
            *(__half2*)(hs_lo + sub * 16) = __floats2half2_rn(hreg[sub * 4 + 0], hreg[sub * 4 + 1]);
            *(__half2*)(hs_hi + sub * 16) = __floats2half2_rn(hreg[sub * 4 + 2], hreg[sub * 4 + 3]);
        }
        __syncthreads();

#pragma unroll
        for (int i = 0; i < 64; i++) ((float*)acc)[i] = 0.0f;

#pragma unroll
        for (int kt = 0; kt < 10; kt++) {
            u32 a0, a1, a2, a3;
            ldsm_x4(a0, a1, a2, a3, a_addr + kt * 32);
#pragma unroll
            for (int gi = 0; gi < 4; gi++) {
#pragma unroll
                for (int sub = 0; sub < 4; sub++) {
                    u32 b0, b1;
                    ldsm_x2t(b0, b1, b_addr + (u32)(kt * 16 * BSTRIDE + (gi * 128 + jq * 32 + sub * 8) * 2));
                    mma16816(acc[gi][sub], a0, a1, a2, a3, b0, b1);
                }
            }
        }
        __syncthreads();

        const float4* bias4 = (const float4*)(sm + SMB_BIAS);
#pragma unroll
        for (int sub = 0; sub < 4; sub++) {
            const int jb = jq * 32 + sub * 8 + 2 * tig;
#pragma unroll
            for (int cc = 0; cc < 4; cc++) {
                int j = jb + (cc & 1);
                float4 b4 = bias4[j];
                float iv = sga(acc[0][sub][cc] + b4.x);
                float fv = sga(acc[1][sub][cc] + b4.y);
                float gv = tapx(acc[2][sub][cc] + b4.z);
                float ov = sga(acc[3][sub][cc] + b4.w);
                int ci = sub * 4 + cc;
                float cn = fv * cst[ci] + iv * gv;
                cst[ci] = cn;
                hreg[ci] = ov * tapx(cn);
            }
        }
    }

#pragma unroll
    for (int half = 0; half < 2; half++) {
        int gr = row0 + rt * 16 + g + half * 8;
        bool hm = (gr < 6144);
        int g2 = hm ? gr : gr - 6144;
        int bb = g2 / 12, pp = g2 - 12 * bb;
        float* fp = g_feat + (size_t)bb * FEATC + (hm ? 768 : 2304) + pp * H3_;
#pragma unroll
        for (int sub = 0; sub < 4; sub++) {
            int j = jq * 32 + sub * 8 + 2 * tig;
            fp[j]     = hreg[sub * 4 + half * 2 + 0];
            fp[j + 1] = hreg[sub * 4 + half * 2 + 1];
        }
    }
}

// ---------------- FC ----------------
__global__ void fc_kernel(const float* __restrict__ cg, const float* __restrict__ Wfc,
                          const float* __restrict__ bfc, float* __restrict__ out)
{
    const int b = blockIdx.x, tid = threadIdx.x;   // 128 threads
    const float* f = g_feat + b * FEATC;
    float a0 = 0.0f, a1 = 0.0f;
    for (int i = tid; i < FEATC; i += 128) {
        float v = f[i];
        a0 = fmaf(v, Wfc[i], a0);
        a1 = fmaf(v, Wfc[FCIN_ + i], a1);
    }
    if (tid < 32) {
        float v = cg[b * 32 + tid];
        a0 = fmaf(v, Wfc[FEATC + tid], a0);
        a1 = fmaf(v, Wfc[FCIN_ + FEATC + tid], a1);
    }
#pragma unroll
    for (int o = 16; o > 0; o >>= 1) {
        a0 += __shfl_down_sync(0xffffffffu, a0, o);
        a1 += __shfl_down_sync(0xffffffffu, a1, o);
    }
    __shared__ float r0[4], r1[4];
    int w = tid >> 5, l = tid & 31;
    if (l == 0) { r0[w] = a0; r1[w] = a1; }
    __syncthreads();
    if (tid == 0) {
        out[b * 2 + 0] = r0[0] + r0[1] + r0[2] + r0[3] + bfc[0];
        out[b * 2 + 1] = r1[0] + r1[1] + r1[2] + r1[3] + bfc[1];
    }
}

// ---------------- kernel_launch ----------------
extern "C" void kernel_launch(void* const* d_in, const int* in_sizes, int n_in,
                              void* d_out, int out_size)
{
    (void)in_sizes; (void)n_in; (void)out_size;
    const float* current_game = (const float*)d_in[0];
    const float* games_home   = (const float*)d_in[1];
    const float* games_away   = (const float*)d_in[2];
    const float* games_vs     = (const float*)d_in[3];
    const float* players_home = (const float*)d_in[4];
    const float* players_away = (const float*)d_in[5];
    const float* Wih1 = (const float*)d_in[6];
    const float* Whh1 = (const float*)d_in[7];
    const float* bih1 = (const float*)d_in[8];
    const float* bhh1 = (const float*)d_in[9];
    const float* Wih2 = (const float*)d_in[10];
    const float* Whh2 = (const float*)d_in[11];
    const float* bih2 = (const float*)d_in[12];
    const float* bhh2 = (const float*)d_in[13];
    const float* Wih3 = (const float*)d_in[14];
    const float* Whh3 = (const float*)d_in[15];
    const float* bih3 = (const float*)d_in[16];
    const float* bhh3 = (const float*)d_in[17];
    const float* Wfc  = (const float*)d_in[18];
    const float* bfc  = (const float*)d_in[19];

    cudaFuncSetAttribute(lstm12_mma, cudaFuncAttributeMaxDynamicSharedMemorySize, SMEM12);
    cudaFuncSetAttribute(lstm3_mma,  cudaFuncAttributeMaxDynamicSharedMemorySize, SMEM3);

    prep_kernel<<<1280, 256>>>(Wih1, Whh1, bih1, bhh1,
                               Wih2, Whh2, bih2, bhh2, bih3, bhh3);
    lstm12_mma<<<96, 256, SMEM12>>>(games_home, games_away, games_vs);
    lstm3_mma<<<384, 256, SMEM3>>>(players_home, players_away, Wih3, Whh3);
    fc_kernel<<<512, 128>>>(current_game, Wfc, bfc, (float*)d_out);
}

// round 9
// speedup vs baseline: 7.3582x; 1.2274x over previous
#include <cuda_runtime.h>
#include <cuda_fp16.h>
#include <cstdint>

#define B_    512
#define T1_   128
#define IN1_  64
#define H1_   256
#define IN3_  32
#define H3_   128
#define T3_   64
#define FCIN_ 3872
#define FEATC 3840

typedef unsigned long long u64;
typedef unsigned int u32;

// ---------------- device scratch ----------------
__device__ __align__(16) __half g_W1h[320 * 1024];   // [k][n], n=gate*256+j, pitch 2048B
__device__ __align__(16) __half g_W2h[320 * 1024];
__device__ __align__(16) float4 g_b1v4[H1_];         // (bi,bf,bg,bo) per j
__device__ __align__(16) float4 g_b2v4[H1_];
__device__ __align__(16) float  g_b3[H3_ * 4];       // [j][(bi,bf,bg,bo)]
__device__ float g_feat[B_ * FEATC];

// ---------------- scalar helpers ----------------
__device__ __forceinline__ float tapx(float x) {           // HW tanh (MUFU)
    float y; asm("tanh.approx.f32 %0, %1;" : "=f"(y) : "f"(x)); return y;
}
__device__ __forceinline__ float sga(float x) {            // sigmoid via tanh
    return fmaf(tapx(0.5f * x), 0.5f, 0.5f);
}
__device__ __forceinline__ u32 smem_u32(const void* p) {
    u32 a;
    asm("{ .reg .u64 t; cvta.to.shared.u64 t, %1; cvt.u32.u64 %0, t; }" : "=r"(a) : "l"(p));
    return a;
}

// ---------------- mma.sync / ldmatrix / cp.async (baseline PTX) ----------------
__device__ __forceinline__ void ldsm_x4(u32& r0, u32& r1, u32& r2, u32& r3, u32 addr) {
    asm volatile("ldmatrix.sync.aligned.m8n8.x4.shared.b16 {%0,%1,%2,%3}, [%4];"
                 : "=r"(r0), "=r"(r1), "=r"(r2), "=r"(r3) : "r"(addr));
}
// x4 trans: lanes 0-15 -> k-rows 0..15 at n_off; lanes 16-31 -> same k-rows at n_off+8.
// regs: {r0,r1} = B-frag of n-tile at n_off, {r2,r3} = n-tile at n_off+8.
__device__ __forceinline__ void ldsm_x4t(u32& r0, u32& r1, u32& r2, u32& r3, u32 addr) {
    asm volatile("ldmatrix.sync.aligned.m8n8.x4.trans.shared.b16 {%0,%1,%2,%3}, [%4];"
                 : "=r"(r0), "=r"(r1), "=r"(r2), "=r"(r3) : "r"(addr));
}
__device__ __forceinline__ void mma16816(float* c, u32 a0, u32 a1, u32 a2, u32 a3,
                                         u32 b0, u32 b1) {
    asm volatile("mma.sync.aligned.m16n8k16.row.col.f32.f16.f16.f32 "
                 "{%0,%1,%2,%3}, {%4,%5,%6,%7}, {%8,%9}, {%0,%1,%2,%3};"
                 : "+f"(c[0]), "+f"(c[1]), "+f"(c[2]), "+f"(c[3])
                 : "r"(a0), "r"(a1), "r"(a2), "r"(a3), "r"(b0), "r"(b1));
}
__device__ __forceinline__ void cp16(u32 saddr, const void* gptr) {
    asm volatile("cp.async.cg.shared.global [%0], [%1], 16;" :: "r"(saddr), "l"(gptr));
}
__device__ __forceinline__ void cp_commit() {
    asm volatile("cp.async.commit_group;" ::: "memory");
}
template<int N> __device__ __forceinline__ void cp_wait() {
    asm volatile("cp.async.wait_group %0;" :: "n"(N) : "memory");
}

// ---------------- roleB (lstm3) smem layout (proven) ----------------
#define ASTRIDE 336
#define BSTRIDE 1040
#define SMB_A    0
#define SMB_BIAS 10752
#define SMB_B    12800           // + 160*1040 = 179200

// ---------------- roleA (lstm12, 32 rows) smem layout ----------------
#define APITCH12  656            // 32 rows x 656B = 20992
#define BPITCH12  2064
#define TILE12    66048          // 32*2064
#define SA_A      0
#define SA_BIAS   20992          // float4[256] = 4096
#define SA_B0     25088
#define SA_B1     (25088 + TILE12)
// roleA total = 25088 + 2*66048 = 157184 < 179200

#define SMEM_MERGED 179200

// ---------------- weight prep ----------------
__global__ void prep_kernel(
    const float* __restrict__ Wih1, const float* __restrict__ Whh1,
    const float* __restrict__ bih1, const float* __restrict__ bhh1,
    const float* __restrict__ Wih2, const float* __restrict__ Whh2,
    const float* __restrict__ bih2, const float* __restrict__ bhh2,
    const float* __restrict__ bih3, const float* __restrict__ bhh3)
{
    int idx = blockIdx.x * blockDim.x + threadIdx.x;   // 327680 threads
    if (idx < 320 * 1024) {
        int k = idx >> 10, n = idx & 1023;
        int tau = n >> 8, j = n & 255;
        int g = tau * H1_ + j;
        float v1 = (k < IN1_) ? Wih1[g * IN1_ + k] : Whh1[g * H1_ + (k - IN1_)];
        float v2 = (k < IN1_) ? Wih2[g * IN1_ + k] : Whh2[g * H1_ + (k - IN1_)];
        g_W1h[idx] = __float2half_rn(v1);
        g_W2h[idx] = __float2half_rn(v2);
    }
    if (idx < H1_) {
        int j = idx;
        g_b1v4[j] = make_float4(bih1[j] + bhh1[j],
                                bih1[H1_ + j] + bhh1[H1_ + j],
                                bih1[2 * H1_ + j] + bhh1[2 * H1_ + j],
                                bih1[3 * H1_ + j] + bhh1[3 * H1_ + j]);
        g_b2v4[j] = make_float4(bih2[j] + bhh2[j],
                                bih2[H1_ + j] + bhh2[H1_ + j],
                                bih2[2 * H1_ + j] + bhh2[2 * H1_ + j],
                                bih2[3 * H1_ + j] + bhh2[3 * H1_ + j]);
    }
    if (idx < H3_ * 4) {
        int tau = idx & 3, j = idx >> 2;
        g_b3[j * 4 + tau] = bih3[tau * H3_ + j] + bhh3[tau * H3_ + j];
    }
}

// ---------------------------------------------------------------------------
// Merged LSTM kernel: 432 blocks x 256 threads.
//   blocks 0..47   : roleA = LSTM1/2, 32 rows/block (b<32: LSTM1, else LSTM2),
//                    B streamed via cp.async (10 circular 32k-tiles, 2 buffers)
//   blocks 48..431 : roleB = LSTM3, 32 rows/block, B smem-resident (proven R7/8)
// ---------------------------------------------------------------------------
__global__ __launch_bounds__(256, 1) void lstm_merged(
    const float* __restrict__ games_home, const float* __restrict__ games_away,
    const float* __restrict__ games_vs,
    const float* __restrict__ ph, const float* __restrict__ pa,
    const float* __restrict__ Wih3, const float* __restrict__ Whh3)
{
    extern __shared__ __align__(16) char sm[];
    const u32 sbase = smem_u32(sm);
    const int tid = threadIdx.x, wid = tid >> 5, lane = tid & 31;

    if (blockIdx.x < 48) {
        // =================== roleA: LSTM1/2, 32 rows ===================
        const int b = blockIdx.x;
        const bool is1 = (b < 32);
        const int row0 = (is1 ? b : (b - 32)) * 32;
        const char* gB = (const char*)(is1 ? g_W1h : g_W2h);

        ((float4*)(sm + SA_BIAS))[tid] = (is1 ? g_b1v4 : g_b2v4)[tid];
        for (int i = tid; i < 32 * APITCH12 / 8; i += 256) ((u64*)(sm + SA_A))[i] = 0ull;

        // x loader: 32 rows x 8 threads/row, 2 float4 chunks each
        const int xr = tid >> 3, xq = tid & 7;
        const int gxr = row0 + xr;
        const float* xrowp = is1 ? ((gxr < 512) ? games_home + (size_t)gxr * (T1_ * IN1_)
                                                : games_away + (size_t)(gxr - 512) * (T1_ * IN1_))
                                 : games_vs + (size_t)gxr * (T1_ * IN1_);
        const float4* xsrc = (const float4*)xrowp + xq;
        char* xdst = sm + SA_A + xr * APITCH12 + xq * 8;

        const int jq = wid;
        const int g = lane >> 2, tig = lane & 3;
        const u32 a_addr = sbase + SA_A + (u32)((lane & 15) * APITCH12 + (lane >> 4) * 16);
        const u32 b_lane = (u32)((lane & 15) * BPITCH12 + (lane >> 4) * 16);

        char* hs[2][2];
#pragma unroll
        for (int rt = 0; rt < 2; rt++) {
            hs[rt][0] = sm + SA_A + (rt * 16 + g) * APITCH12 + (IN1_ + jq * 32 + 2 * tig) * 2;
            hs[rt][1] = hs[rt][0] + 8 * APITCH12;
        }

        float acc[2][4][4][4];
        float cst[32], hreg[32];
#pragma unroll
        for (int i = 0; i < 32; i++) { cst[i] = 0.0f; hreg[i] = 0.0f; }

        const u32 bufs[2] = { sbase + SA_B0, sbase + SA_B1 };
#pragma unroll
        for (int pt = 0; pt < 2; pt++) {
#pragma unroll
            for (int q = 0; q < 16; q++) {
                int c = tid + 256 * q;
                int row = c >> 7, col = (c & 127) * 16;
                cp16(bufs[pt] + (u32)(row * BPITCH12 + col), gB + (pt * 32 + row) * 2048 + col);
            }
            cp_commit();
        }
        __syncthreads();

        for (int t = 0; t < T1_; t++) {
            // phase 1: x_t + h_{t-1} -> A
            float4 xv0 = __ldg(xsrc + t * 16);
            float4 xv1 = __ldg(xsrc + t * 16 + 8);
            *(__half2*)(xdst)      = __floats2half2_rn(xv0.x, xv0.y);
            *(__half2*)(xdst + 4)  = __floats2half2_rn(xv0.z, xv0.w);
            *(__half2*)(xdst + 64) = __floats2half2_rn(xv1.x, xv1.y);
            *(__half2*)(xdst + 68) = __floats2half2_rn(xv1.z, xv1.w);
#pragma unroll
            for (int rt = 0; rt < 2; rt++)
#pragma unroll
                for (int sub = 0; sub < 4; sub++) {
                    *(__half2*)(hs[rt][0] + sub * 16) =
                        __floats2half2_rn(hreg[rt * 16 + sub * 4 + 0], hreg[rt * 16 + sub * 4 + 1]);
                    *(__half2*)(hs[rt][1] + sub * 16) =
                        __floats2half2_rn(hreg[rt * 16 + sub * 4 + 2], hreg[rt * 16 + sub * 4 + 3]);
                }
            __syncthreads();

#pragma unroll
            for (int i = 0; i < 128; i++) ((float*)acc)[i] = 0.0f;

            // phase 2: K loop over 10 streamed tiles
            for (int kt = 0; kt < 10; kt++) {
                const u32 buf = bufs[kt & 1];
                cp_wait<1>();
                __syncthreads();
#pragma unroll
                for (int ks = 0; ks < 2; ks++) {
                    u32 a0[4], a1[4];
                    ldsm_x4(a0[0], a0[1], a0[2], a0[3], a_addr + (u32)((kt * 2 + ks) * 32));
                    ldsm_x4(a1[0], a1[1], a1[2], a1[3],
                            a_addr + (u32)(16 * APITCH12 + (kt * 2 + ks) * 32));
                    const u32 bk = buf + b_lane + (u32)(ks * 16 * BPITCH12);
#pragma unroll
                    for (int gi = 0; gi < 4; gi++) {
#pragma unroll
                        for (int sp = 0; sp < 2; sp++) {
                            u32 b0, b1, b2, b3;
                            ldsm_x4t(b0, b1, b2, b3,
                                     bk + (u32)((gi * 256 + jq * 32 + sp * 16) * 2));
                            mma16816(acc[0][gi][2 * sp],     a0[0], a0[1], a0[2], a0[3], b0, b1);
                            mma16816(acc[0][gi][2 * sp + 1], a0[0], a0[1], a0[2], a0[3], b2, b3);
                            mma16816(acc[1][gi][2 * sp],     a1[0], a1[1], a1[2], a1[3], b0, b1);
                            mma16816(acc[1][gi][2 * sp + 1], a1[0], a1[1], a1[2], a1[3], b2, b3);
                        }
                    }
                }
                __syncthreads();
                int nt = (kt + 2) % 10;
#pragma unroll
                for (int q = 0; q < 16; q++) {
                    int c = tid + 256 * q;
                    int row = c >> 7, col = (c & 127) * 16;
                    cp16(buf + (u32)(row * BPITCH12 + col), gB + (nt * 32 + row) * 2048 + col);
                }
                cp_commit();
            }

            // phase 3: cell update
            const float4* bias4 = (const float4*)(sm + SA_BIAS);
#pragma unroll
            for (int rt = 0; rt < 2; rt++)
#pragma unroll
                for (int sub = 0; sub < 4; sub++) {
                    const int jb = jq * 32 + sub * 8 + 2 * tig;
#pragma unroll
                    for (int cc = 0; cc < 4; cc++) {
                        int j = jb + (cc & 1);
                        float4 b4 = bias4[j];
                        float iv = sga(acc[rt][0][sub][cc] + b4.x);
                        float fv = sga(acc[rt][1][sub][cc] + b4.y);
                        float gv = tapx(acc[rt][2][sub][cc] + b4.z);
                        float ov = sga(acc[rt][3][sub][cc] + b4.w);
                        int ci = rt * 16 + sub * 4 + cc;
                        float cn = fv * cst[ci] + iv * gv;
                        cst[ci] = cn;
                        hreg[ci] = ov * tapx(cn);
                    }
                }
        }

        // final h -> g_feat
#pragma unroll
        for (int rt = 0; rt < 2; rt++)
#pragma unroll
            for (int half = 0; half < 2; half++) {
                int gr = row0 + rt * 16 + g + half * 8;
                float* fp;
                if (is1) fp = g_feat + (size_t)(gr & 511) * FEATC + ((gr < 512) ? 0 : 256);
                else     fp = g_feat + (size_t)gr * FEATC + 512;
#pragma unroll
                for (int sub = 0; sub < 4; sub++) {
                    int j = jq * 32 + sub * 8 + 2 * tig;
                    fp[j]     = hreg[rt * 16 + sub * 4 + half * 2 + 0];
                    fp[j + 1] = hreg[rt * 16 + sub * 4 + half * 2 + 1];
                }
            }
    } else {
        // =================== roleB: LSTM3, 32 rows (proven) ===================
        const int row0 = (blockIdx.x - 48) * 32;

        for (int idx = tid; idx < 512 * 160; idx += 256) {
            int n = idx / 160, k = idx - n * 160;
            float v = (k < IN3_) ? Wih3[n * IN3_ + k] : Whh3[n * H3_ + (k - IN3_)];
            *(__half*)(sm + SMB_B + k * BSTRIDE + n * 2) = __float2half_rn(v);
        }
        for (int i = tid; i < 512; i += 256)
            ((float*)(sm + SMB_BIAS))[i] = g_b3[i];

        const int xr = tid >> 3, xq = tid & 7;
        const int gxr = row0 + xr;
        const bool hmx = (gxr < 6144);
        const int gx2 = hmx ? gxr : gxr - 6144;
        const float4* xsrc = (const float4*)((hmx ? ph : pa) + (size_t)gx2 * (T3_ * IN3_)) + xq;
        char* xdst = sm + SMB_A + xr * ASTRIDE + xq * 8;

        const int rt = wid >> 2, jq = wid & 3;
        const int g = lane >> 2, tig = lane & 3;

        const u32 a_addr = sbase + SMB_A + (u32)((rt * 16 + (lane & 15)) * ASTRIDE + (lane >> 4) * 16);
        const u32 b_addr = sbase + SMB_B + (u32)((lane & 15) * BSTRIDE + (lane >> 4) * 16);

        char* hs_lo = sm + SMB_A + (rt * 16 + g) * ASTRIDE + (IN3_ + jq * 32 + 2 * tig) * 2;
        char* hs_hi = hs_lo + 8 * ASTRIDE;

        float acc[4][4][4];
        float cst[16], hreg[16];
#pragma unroll
        for (int i = 0; i < 16; i++) { cst[i] = 0.0f; hreg[i] = 0.0f; }

        __syncthreads();

        for (int t = 0; t < T3_; t++) {
            float4 xv = __ldg(xsrc + t * 8);
            *(__half2*)(xdst)     = __floats2half2_rn(xv.x, xv.y);
            *(__half2*)(xdst + 4) = __floats2half2_rn(xv.z, xv.w);
#pragma unroll
            for (int sub = 0; sub < 4; sub++) {
                *(__half2*)(hs_lo + sub * 16) = __floats2half2_rn(hreg[sub * 4 + 0], hreg[sub * 4 + 1]);
                *(__half2*)(hs_hi + sub * 16) = __floats2half2_rn(hreg[sub * 4 + 2], hreg[sub * 4 + 3]);
            }
            __syncthreads();

#pragma unroll
            for (int i = 0; i < 64; i++) ((float*)acc)[i] = 0.0f;

#pragma unroll
            for (int kt = 0; kt < 10; kt++) {
                u32 a0, a1, a2, a3;
                ldsm_x4(a0, a1, a2, a3, a_addr + kt * 32);
#pragma unroll
                for (int gi = 0; gi < 4; gi++) {
#pragma unroll
                    for (int sp = 0; sp < 2; sp++) {
                        u32 b0, b1, b2, b3;
                        ldsm_x4t(b0, b1, b2, b3,
                                 b_addr + (u32)(kt * 16 * BSTRIDE + (gi * 128 + jq * 32 + sp * 16) * 2));
                        mma16816(acc[gi][2 * sp],     a0, a1, a2, a3, b0, b1);
                        mma16816(acc[gi][2 * sp + 1], a0, a1, a2, a3, b2, b3);
                    }
                }
            }
            __syncthreads();

            const float4* bias4 = (const float4*)(sm + SMB_BIAS);
#pragma unroll
            for (int sub = 0; sub < 4; sub++) {
                const int jb = jq * 32 + sub * 8 + 2 * tig;
#pragma unroll
                for (int cc = 0; cc < 4; cc++) {
                    int j = jb + (cc & 1);
                    float4 b4 = bias4[j];
                    float iv = sga(acc[0][sub][cc] + b4.x);
                    float fv = sga(acc[1][sub][cc] + b4.y);
                    float gv = tapx(acc[2][sub][cc] + b4.z);
                    float ov = sga(acc[3][sub][cc] + b4.w);
                    int ci = sub * 4 + cc;
                    float cn = fv * cst[ci] + iv * gv;
                    cst[ci] = cn;
                    hreg[ci] = ov * tapx(cn);
                }
            }
        }

#pragma unroll
        for (int half = 0; half < 2; half++) {
            int gr = row0 + rt * 16 + g + half * 8;
            bool hm = (gr < 6144);
            int g2 = hm ? gr : gr - 6144;
            int bb = g2 / 12, pp = g2 - 12 * bb;
            float* fp = g_feat + (size_t)bb * FEATC + (hm ? 768 : 2304) + pp * H3_;
#pragma unroll
            for (int sub = 0; sub < 4; sub++) {
                int j = jq * 32 + sub * 8 + 2 * tig;
                fp[j]     = hreg[sub * 4 + half * 2 + 0];
                fp[j + 1] = hreg[sub * 4 + half * 2 + 1];
            }
        }
    }
}

// ---------------- FC ----------------
__global__ void fc_kernel(const float* __restrict__ cg, const float* __restrict__ Wfc,
                          const float* __restrict__ bfc, float* __restrict__ out)
{
    const int b = blockIdx.x, tid = threadIdx.x;   // 128 threads
    const float* f = g_feat + b * FEATC;
    float a0 = 0.0f, a1 = 0.0f;
    for (int i = tid; i < FEATC; i += 128) {
        float v = f[i];
        a0 = fmaf(v, Wfc[i], a0);
        a1 = fmaf(v, Wfc[FCIN_ + i], a1);
    }
    if (tid < 32) {
        float v = cg[b * 32 + tid];
        a0 = fmaf(v, Wfc[FEATC + tid], a0);
        a1 = fmaf(v, Wfc[FCIN_ + FEATC + tid], a1);
    }
#pragma unroll
    for (int o = 16; o > 0; o >>= 1) {
        a0 += __shfl_down_sync(0xffffffffu, a0, o);
        a1 += __shfl_down_sync(0xffffffffu, a1, o);
    }
    __shared__ float r0[4], r1[4];
    int w = tid >> 5, l = tid & 31;
    if (l == 0) { r0[w] = a0; r1[w] = a1; }
    __syncthreads();
    if (tid == 0) {
        out[b * 2 + 0] = r0[0] + r0[1] + r0[2] + r0[3] + bfc[0];
        out[b * 2 + 1] = r1[0] + r1[1] + r1[2] + r1[3] + bfc[1];
    }
}

// ---------------- kernel_launch ----------------
extern "C" void kernel_launch(void* const* d_in, const int* in_sizes, int n_in,
                              void* d_out, int out_size)
{
    (void)in_sizes; (void)n_in; (void)out_size;
    const float* current_game = (const float*)d_in[0];
    const float* games_home   = (const float*)d_in[1];
    const float* games_away   = (const float*)d_in[2];
    const float* games_vs     = (const float*)d_in[3];
    const float* players_home = (const float*)d_in[4];
    const float* players_away = (const float*)d_in[5];
    const float* Wih1 = (const float*)d_in[6];
    const float* Whh1 = (const float*)d_in[7];
    const float* bih1 = (const float*)d_in[8];
    const float* bhh1 = (const float*)d_in[9];
    const float* Wih2 = (const float*)d_in[10];
    const float* Whh2 = (const float*)d_in[11];
    const float* bih2 = (const float*)d_in[12];
    const float* bhh2 = (const float*)d_in[13];
    const float* Wih3 = (const float*)d_in[14];
    const float* Whh3 = (const float*)d_in[15];
    const float* bih3 = (const float*)d_in[16];
    const float* bhh3 = (const float*)d_in[17];
    const float* Wfc  = (const float*)d_in[18];
    const float* bfc  = (const float*)d_in[19];

    cudaFuncSetAttribute(lstm_merged, cudaFuncAttributeMaxDynamicSharedMemorySize, SMEM_MERGED);

    prep_kernel<<<1280, 256>>>(Wih1, Whh1, bih1, bhh1,
                               Wih2, Whh2, bih2, bhh2, bih3, bhh3);
    lstm_merged<<<432, 256, SMEM_MERGED>>>(games_home, games_away, games_vs,
                                           players_home, players_away, Wih3, Whh3);
    fc_kernel<<<512, 128>>>(current_game, Wfc, bfc, (float*)d_out);
}